// round 14
// baseline (speedup 1.0000x reference)
#include <cuda_runtime.h>

// Problem constants (fixed by the reference setup)
#define NBATCH 32
#define NATOM 256
#define PAIRS_PB 15360
#define NN (NBATCH * PAIRS_PB)      // 491520 total pairs
#define TOTNATOM (NBATCH * NATOM)   // 8192
#define NWAVE 8
#define NSYM 10                     // symmetric channels: 1, x,y,z, xx,xy,xz,yy,yz,zz
#define NORBIT 128
#define CAP 96                      // bin capacity (mean 60, sigma 7.7)
#define APB 8                       // atoms per block (gather)
#define HSTRIDE 80                  // logical floats per atom slab: 10*8
#define QSTRIDE 84                  // padded quarter-slab stride (bank-clean)
#define PBATCH 4                    // pairs per thread in pair_kernel

// Per-atom pair bins: record = {ux|sp(2 low bits), uy, uz, d} = 1 float4 (16 B)
__device__ float4 g_rec[(size_t)TOTNATOM * CAP];       // 12.6 MB (L2-resident)
__device__ int    g_cnt[TOTNATOM];                     // zero-init (.bss); gather resets
// Overflow fallback accumulator [atom][c(10)][w(8)]; gather re-zeroes on use
__device__ float4 g_S[TOTNATOM * (NSYM * NWAVE / 4)];  // 2.6 MB

__device__ __forceinline__ void red_add_v4(float4* ptr, float a, float b, float c, float d) {
    asm volatile("red.global.add.v4.f32 [%0], {%1, %2, %3, %4};"
                 :: "l"(ptr), "f"(a), "f"(b), "f"(c), "f"(d) : "memory");
}
__device__ __forceinline__ float ex2_approx(float x) {
    float r;
    asm("ex2.approx.f32 %0, %1;" : "=f"(r) : "f"(x));
    return r;
}
#define MUL_F32X2(d, a, b) \
    asm("mul.rn.f32x2 %0, %1, %2;" : "=l"(d) : "l"(a), "l"(b))
#define FMA_F32X2(d, a, b, c) \
    asm("fma.rn.f32x2 %0, %1, %2, %3;" : "=l"(d) : "l"(a), "l"(b), "l"(c))
#define PACK2(d, lo, hi) \
    asm("mov.b64 %0, {%1, %2};" : "=l"(d) : "f"(lo), "f"(hi))
#define UNPACK2(lo, hi, s) \
    asm("mov.b64 {%0, %1}, %2;" : "=f"(lo), "=f"(hi) : "l"(s))

// ---------------------------------------------------------------------------
// Kernel 1: per-pair geometry + binning, 4 pairs/thread, with batch-resident
// smem caches for cart (float4) + species (R9-proven).
// ---------------------------------------------------------------------------
__global__ void __launch_bounds__(256) pair_kernel(
    const float* __restrict__ cart,        // (totnatom, 3)
    const int*   __restrict__ species,     // (totnatom,)
    const int*   __restrict__ atom_index,  // (2, NN) flattened
    const float* __restrict__ shifts,      // (NN, 3)
    const float* __restrict__ rs,          // (NTYPE, 8)
    const float* __restrict__ inta,        // (NTYPE, 8)
    const float* __restrict__ params)      // (NTYPE, 8)
{
    const int QT  = NN / PBATCH;           // 122880
    const int tid = threadIdx.x;
    const int p0  = blockIdx.x * 256;
    const int t   = p0 + tid;

    __shared__ float4 Csm[PBATCH][NATOM];  // 16 KB
    __shared__ int    Ssp[PBATCH][NATOM];  // 4 KB

    int bk[PBATCH];
#pragma unroll
    for (int k = 0; k < PBATCH; k++) {
        bk[k] = (p0 + k * QT) / PAIRS_PB;  // batch of stream k (block-constant)
        const float* cr = cart + (size_t)(bk[k] * NATOM + tid) * 3;
        Csm[k][tid] = make_float4(__ldg(cr), __ldg(cr + 1), __ldg(cr + 2), 0.f);
        Ssp[k][tid] = __ldg(&species[bk[k] * NATOM + tid]);
    }
    __syncthreads();

    int pp[PBATCH], il[PBATCH], jl[PBATCH], slot[PBATCH];

#pragma unroll
    for (int k = 0; k < PBATCH; k++) {
        int p = t + k * QT;
        pp[k] = p;
        il[k] = __ldg(&atom_index[p]);          // local (0..255)
        jl[k] = __ldg(&atom_index[NN + p]);
    }

#pragma unroll
    for (int k = 0; k < PBATCH; k++)
        slot[k] = atomicAdd(&g_cnt[bk[k] * NATOM + il[k]], 1);

    float dx[PBATCH], dy[PBATCH], dz[PBATCH];
    int sp[PBATCH];
#pragma unroll
    for (int k = 0; k < PBATCH; k++) {
        float4 ci = Csm[k][il[k]];
        float4 cj = Csm[k][jl[k]];
        dx[k] = ci.x - cj.x + __ldg(&shifts[3 * pp[k] + 0]);
        dy[k] = ci.y - cj.y + __ldg(&shifts[3 * pp[k] + 1]);
        dz[k] = ci.z - cj.z + __ldg(&shifts[3 * pp[k] + 2]);
        sp[k] = Ssp[k][jl[k]];
    }

#pragma unroll
    for (int k = 0; k < PBATCH; k++) {
        float d2  = dx[k] * dx[k] + dy[k] * dy[k] + dz[k] * dz[k];
        float inv = rsqrtf(d2);
        float d   = d2 * inv;                 // |r|
        float ux = dx[k] * inv, uy = dy[k] * inv, uz = dz[k] * inv;
        int ig = bk[k] * NATOM + il[k];       // global center atom

        if (slot[k] < CAP) {
            unsigned uxb = (__float_as_uint(ux) & ~3u) | (unsigned)sp[k];
            g_rec[(size_t)ig * CAP + slot[k]] = make_float4(__uint_as_float(uxb), uy, uz, d);
        } else {
            // Overflow fallback (expected never taken): exact red-atomic scatter
            float rc[NWAVE];
#pragma unroll
            for (int w = 0; w < NWAVE; w++) {
                float tt = d - __ldg(&rs[sp[k] * NWAVE + w]);
                rc[w] = __expf(__ldg(&inta[sp[k] * NWAVE + w]) * tt * tt) * __ldg(&params[sp[k] * NWAVE + w]);
            }
            float ang[NSYM] = {1.f, ux, uy, uz,
                               ux * ux, ux * uy, ux * uz, uy * uy, uy * uz, uz * uz};
            float4* Sa = g_S + (size_t)ig * (NSYM * NWAVE / 4);
#pragma unroll
            for (int c = 0; c < NSYM; c++) {
                float a = ang[c];
                red_add_v4(&Sa[2 * c + 0], a * rc[0], a * rc[1], a * rc[2], a * rc[3]);
                red_add_v4(&Sa[2 * c + 1], a * rc[4], a * rc[5], a * rc[6], a * rc[7]);
            }
        }
    }
}

// ---------------------------------------------------------------------------
// Kernel 2: gather + hyper contraction. 8 atoms/block, 256 THREADS, grid 1024.
// Phase 1: 32 threads/atom = ONE WARP/atom = (quarter 0..3) x (w 0..7);
//   ~15-record loop per thread; Horner radial with ONE LDS.128 table lookup.
// Phase 2: combine quarters into PACKED atom-pair layout (sqrt weights folded).
// Phase 3: packed fma.rn.f32x2; thread = (orbit m, atom-half), 2 pairs each.
// Also resets g_cnt (and g_S if overflow) for the next graph replay.
// ---------------------------------------------------------------------------
__global__ void __launch_bounds__(256, 5) gather_kernel(
    const float* __restrict__ rs,      // (NTYPE, 8)
    const float* __restrict__ inta,    // (NTYPE, 8)
    const float* __restrict__ params,  // (NTYPE, 8)
    const float* __restrict__ hyper,   // (3, 8, 128)
    float* __restrict__ out)           // (totnatom, 128)
{
    const int tid = threadIdx.x;
    const int la  = tid >> 5;          // local atom 0..7 (one warp per atom)
    const int q   = (tid >> 3) & 3;    // bin quarter 0..3
    const int w   = tid & 7;           // wave index 0..7
    const int a   = blockIdx.x * APB + la;

    __shared__ __align__(16) float4 Tbl[32];                 // {c2,c1,c0,0} per (sp,w)
    __shared__ float Ssm[APB * 4 * QSTRIDE];                 // 10.75 KB (quarters)
    __shared__ __align__(16) float2 Pk[APB / 2][NSYM * NWAVE];   // 2.5 KB packed

    if (tid < 32) {
        const float L2E = 1.4426950408889634f;
        float R = __ldg(&rs[tid]);
        float A = __ldg(&inta[tid]) * L2E;
        float P = __ldg(&params[tid]);
        Tbl[tid] = make_float4(A, -2.f * A * R, A * R * R + __log2f(P), 0.f);
    }
    __syncthreads();

    // ---- Phase 1: per-(atom, quarter, w) symmetric moment accumulation ----
    const int n  = g_cnt[a];           // warp-uniform (whole warp = this atom)
    const int nc = min(n, CAP);
    if ((tid & 31) == 0) g_cnt[a] = 0; // warp-synchronous reset after read

    float acc[NSYM];
    if (n > CAP && q == 0 && (tid & 31) < 8) {   // overflow init (lanes w=0..7)
        float* gs = (float*)(g_S + (size_t)a * (NSYM * NWAVE / 4));
#pragma unroll
        for (int c = 0; c < NSYM; c++) {
            acc[c] = gs[c * NWAVE + w];
            gs[c * NWAVE + w] = 0.f;
        }
    } else {
#pragma unroll
        for (int c = 0; c < NSYM; c++) acc[c] = 0.f;
    }

    const float4* rec = g_rec + (size_t)a * CAP;
#pragma unroll 4
    for (int p = q; p < nc; p += 4) {
        float4 r = __ldg(&rec[p]);                 // broadcast across the 8 w-threads
        unsigned uxb = __float_as_uint(r.x);
        int sp8 = (int)(uxb & 3u) * NWAVE + w;
        float ux = __uint_as_float(uxb & ~3u);
        float4 cf = Tbl[sp8];                      // ONE LDS.128
        float rc = ex2_approx(fmaf(fmaf(cf.x, r.w, cf.y), r.w, cf.z));

        acc[0] += rc;
        float tx = rc * ux, ty = rc * r.y, tz = rc * r.z;
        acc[1] += tx;       acc[2] += ty;       acc[3] += tz;
        acc[4] += tx * ux;  acc[5] += tx * r.y;  acc[6] += tx * r.z;
        acc[7] += ty * r.y; acc[8] += ty * r.z;  acc[9] += tz * r.z;
    }

    // ---- Phase 2: stash quarters, combine into packed pair layout ----
#pragma unroll
    for (int c = 0; c < NSYM; c++)
        Ssm[(la * 4 + q) * QSTRIDE + c * NWAVE + w] = acc[c];
    __syncthreads();

    {
        // channel weights {1,1,1,1,1,2,2,1,2,1} -> sqrt folded into S
        const float SQ2 = 1.41421356237309515f;
        const float scl[NSYM] = {1.f, 1.f, 1.f, 1.f, 1.f, SQ2, SQ2, 1.f, SQ2, 1.f};
#pragma unroll
        for (int idx = tid; idx < APB * HSTRIDE; idx += 256) {
            int at = idx / HSTRIDE;
            int cw = idx - at * HSTRIDE;
            float v = Ssm[(at * 4 + 0) * QSTRIDE + cw] + Ssm[(at * 4 + 1) * QSTRIDE + cw]
                    + Ssm[(at * 4 + 2) * QSTRIDE + cw] + Ssm[(at * 4 + 3) * QSTRIDE + cw];
            ((float*)&Pk[at >> 1][cw])[at & 1] = v * scl[cw >> 3];
        }
    }
    __syncthreads();

    // ---- Phase 3: packed f32x2; thread = (orbit m, atom-half ah) ----
    const int m  = tid & 127;
    const int ah = tid >> 7;           // 0 -> pairs {0,1}, 1 -> pairs {2,3}
    unsigned long long hp[3][NWAVE];   // h replicated into both packed halves
#pragma unroll
    for (int k = 0; k < 3; k++)
#pragma unroll
        for (int v = 0; v < NWAVE; v++) {
            float hv = __ldg(&hyper[(k * NWAVE + v) * NORBIT + m]);
            PACK2(hp[k][v], hv, hv);
        }

    const int k_of[NSYM] = {0, 1, 1, 1, 2, 2, 2, 2, 2, 2};

#pragma unroll
    for (int i = 0; i < 2; i++) {
        const int pr = ah * 2 + i;
        const ulonglong2* S2 = (const ulonglong2*)Pk[pr];
        unsigned long long dens;
        PACK2(dens, 0.f, 0.f);
#pragma unroll
        for (int c = 0; c < NSYM; c++) {
            const int k = k_of[c];
            ulonglong2 q0 = S2[c * 4 + 0];   // packed pairs for w=0,1
            ulonglong2 q1 = S2[c * 4 + 1];   // w=2,3
            ulonglong2 q2 = S2[c * 4 + 2];   // w=4,5
            ulonglong2 q3 = S2[c * 4 + 3];   // w=6,7
            unsigned long long tp;
            MUL_F32X2(tp, q0.x, hp[k][0]);
            FMA_F32X2(tp, q0.y, hp[k][1], tp);
            FMA_F32X2(tp, q1.x, hp[k][2], tp);
            FMA_F32X2(tp, q1.y, hp[k][3], tp);
            FMA_F32X2(tp, q2.x, hp[k][4], tp);
            FMA_F32X2(tp, q2.y, hp[k][5], tp);
            FMA_F32X2(tp, q3.x, hp[k][6], tp);
            FMA_F32X2(tp, q3.y, hp[k][7], tp);
            FMA_F32X2(dens, tp, tp, dens);
        }
        float d0, d1;
        UNPACK2(d0, d1, dens);
        const int a0 = blockIdx.x * APB + 2 * pr;
        out[a0 * NORBIT + m]       = d0;
        out[(a0 + 1) * NORBIT + m] = d1;
    }
}

// ---------------------------------------------------------------------------
// Launch (2 kernels; counters self-reset inside gather)
// ---------------------------------------------------------------------------
extern "C" void kernel_launch(void* const* d_in, const int* in_sizes, int n_in,
                              void* d_out, int out_size) {
    const float* cart       = (const float*)d_in[0];
    // d_in[1] = numatoms (unused by the reference math)
    const int*   species    = (const int*)  d_in[2];
    const int*   atom_index = (const int*)  d_in[3];
    const float* shifts     = (const float*)d_in[4];
    const float* rs         = (const float*)d_in[5];
    const float* inta       = (const float*)d_in[6];
    const float* params     = (const float*)d_in[7];
    const float* hyper      = (const float*)d_in[8];
    float* out = (float*)d_out;

    pair_kernel<<<NN / PBATCH / 256, 256>>>(cart, species, atom_index, shifts,
                                            rs, inta, params);
    gather_kernel<<<TOTNATOM / APB, 256>>>(rs, inta, params, hyper, out);
}

// round 15
// speedup vs baseline: 1.1743x; 1.1743x over previous
#include <cuda_runtime.h>

// Problem constants (fixed by the reference setup)
#define NBATCH 32
#define NATOM 256
#define PAIRS_PB 15360
#define NN (NBATCH * PAIRS_PB)      // 491520 total pairs
#define TOTNATOM (NBATCH * NATOM)   // 8192
#define NWAVE 8
#define NSYM 10                     // symmetric channels: 1, x,y,z, xx,xy,xz,yy,yz,zz
#define NORBIT 128
#define CAP 96                      // bin capacity (mean 60, sigma 7.7)
#define APB 8                       // atoms per block (gather)
#define HSTRIDE 80                  // logical floats per atom slab: 10*8
#define QSTRIDE 84                  // padded quarter-slab stride (bank-clean)
#define PBATCH 4                    // pairs per thread in pair_kernel

// Per-atom pair bins: record = {ux|sp(2 low bits), uy, uz, d} = 1 float4 (16 B)
__device__ float4 g_rec[(size_t)TOTNATOM * CAP];       // 12.6 MB (L2-resident)
__device__ int    g_cnt[TOTNATOM];                     // zero-init (.bss); gather resets
// Overflow fallback accumulator [atom][c(10)][w(8)]; gather re-zeroes on use
__device__ float4 g_S[TOTNATOM * (NSYM * NWAVE / 4)];  // 2.6 MB

__device__ __forceinline__ void red_add_v4(float4* ptr, float a, float b, float c, float d) {
    asm volatile("red.global.add.v4.f32 [%0], {%1, %2, %3, %4};"
                 :: "l"(ptr), "f"(a), "f"(b), "f"(c), "f"(d) : "memory");
}
__device__ __forceinline__ float ex2_approx(float x) {
    float r;
    asm("ex2.approx.f32 %0, %1;" : "=f"(r) : "f"(x));
    return r;
}
#define MUL_F32X2(d, a, b) \
    asm("mul.rn.f32x2 %0, %1, %2;" : "=l"(d) : "l"(a), "l"(b))
#define FMA_F32X2(d, a, b, c) \
    asm("fma.rn.f32x2 %0, %1, %2, %3;" : "=l"(d) : "l"(a), "l"(b), "l"(c))
#define PACK2(d, lo, hi) \
    asm("mov.b64 %0, {%1, %2};" : "=l"(d) : "f"(lo), "f"(hi))
#define UNPACK2(lo, hi, s) \
    asm("mov.b64 {%0, %1}, %2;" : "=f"(lo), "=f"(hi) : "l"(s))

// ---------------------------------------------------------------------------
// Kernel 1: per-pair geometry + binning, 4 pairs/thread, with batch-resident
// smem caches for cart (float4) + species (R9-proven).
// ---------------------------------------------------------------------------
__global__ void __launch_bounds__(256) pair_kernel(
    const float* __restrict__ cart,        // (totnatom, 3)
    const int*   __restrict__ species,     // (totnatom,)
    const int*   __restrict__ atom_index,  // (2, NN) flattened
    const float* __restrict__ shifts,      // (NN, 3)
    const float* __restrict__ rs,          // (NTYPE, 8)
    const float* __restrict__ inta,        // (NTYPE, 8)
    const float* __restrict__ params)      // (NTYPE, 8)
{
    const int QT  = NN / PBATCH;           // 122880
    const int tid = threadIdx.x;
    const int p0  = blockIdx.x * 256;
    const int t   = p0 + tid;

    __shared__ float4 Csm[PBATCH][NATOM];  // 16 KB
    __shared__ int    Ssp[PBATCH][NATOM];  // 4 KB

    int bk[PBATCH];
#pragma unroll
    for (int k = 0; k < PBATCH; k++) {
        bk[k] = (p0 + k * QT) / PAIRS_PB;  // batch of stream k (block-constant)
        const float* cr = cart + (size_t)(bk[k] * NATOM + tid) * 3;
        Csm[k][tid] = make_float4(__ldg(cr), __ldg(cr + 1), __ldg(cr + 2), 0.f);
        Ssp[k][tid] = __ldg(&species[bk[k] * NATOM + tid]);
    }
    __syncthreads();

    int pp[PBATCH], il[PBATCH], jl[PBATCH], slot[PBATCH];

#pragma unroll
    for (int k = 0; k < PBATCH; k++) {
        int p = t + k * QT;
        pp[k] = p;
        il[k] = __ldg(&atom_index[p]);          // local (0..255)
        jl[k] = __ldg(&atom_index[NN + p]);
    }

#pragma unroll
    for (int k = 0; k < PBATCH; k++)
        slot[k] = atomicAdd(&g_cnt[bk[k] * NATOM + il[k]], 1);

    float dx[PBATCH], dy[PBATCH], dz[PBATCH];
    int sp[PBATCH];
#pragma unroll
    for (int k = 0; k < PBATCH; k++) {
        float4 ci = Csm[k][il[k]];
        float4 cj = Csm[k][jl[k]];
        dx[k] = ci.x - cj.x + __ldg(&shifts[3 * pp[k] + 0]);
        dy[k] = ci.y - cj.y + __ldg(&shifts[3 * pp[k] + 1]);
        dz[k] = ci.z - cj.z + __ldg(&shifts[3 * pp[k] + 2]);
        sp[k] = Ssp[k][jl[k]];
    }

#pragma unroll
    for (int k = 0; k < PBATCH; k++) {
        float d2  = dx[k] * dx[k] + dy[k] * dy[k] + dz[k] * dz[k];
        float inv = rsqrtf(d2);
        float d   = d2 * inv;                 // |r|
        float ux = dx[k] * inv, uy = dy[k] * inv, uz = dz[k] * inv;
        int ig = bk[k] * NATOM + il[k];       // global center atom

        if (slot[k] < CAP) {
            unsigned uxb = (__float_as_uint(ux) & ~3u) | (unsigned)sp[k];
            g_rec[(size_t)ig * CAP + slot[k]] = make_float4(__uint_as_float(uxb), uy, uz, d);
        } else {
            // Overflow fallback (expected never taken): exact red-atomic scatter
            float rc[NWAVE];
#pragma unroll
            for (int w = 0; w < NWAVE; w++) {
                float tt = d - __ldg(&rs[sp[k] * NWAVE + w]);
                rc[w] = __expf(__ldg(&inta[sp[k] * NWAVE + w]) * tt * tt) * __ldg(&params[sp[k] * NWAVE + w]);
            }
            float ang[NSYM] = {1.f, ux, uy, uz,
                               ux * ux, ux * uy, ux * uz, uy * uy, uy * uz, uz * uz};
            float4* Sa = g_S + (size_t)ig * (NSYM * NWAVE / 4);
#pragma unroll
            for (int c = 0; c < NSYM; c++) {
                float a = ang[c];
                red_add_v4(&Sa[2 * c + 0], a * rc[0], a * rc[1], a * rc[2], a * rc[3]);
                red_add_v4(&Sa[2 * c + 1], a * rc[4], a * rc[5], a * rc[6], a * rc[7]);
            }
        }
    }
}

// ---------------------------------------------------------------------------
// Kernel 2: gather + hyper contraction. 8 atoms/block, 128 threads, grid 1024.
// Phase 1: 16 threads/atom = (quarter 0..3) x (wj 0..3); EACH LANE HANDLES
//   TWO WAVES (wj and wj+4), so the record loop is ~15 iterations and the
//   per-record overhead (unpack/addressing/loop) is amortized over 2 waves.
//   Horner radial: rc = ex2(c2*d^2 + c1*d + c0), one LDS.128 per (record,w).
// Phase 2: combine quarters into PACKED atom-pair layout (sqrt weights folded).
// Phase 3: packed fma.rn.f32x2; thread = orbit column m (R9-proven; no reg cap).
// Also resets g_cnt (and g_S if overflow) for the next graph replay.
// ---------------------------------------------------------------------------
__global__ void __launch_bounds__(128) gather_kernel(
    const float* __restrict__ rs,      // (NTYPE, 8)
    const float* __restrict__ inta,    // (NTYPE, 8)
    const float* __restrict__ params,  // (NTYPE, 8)
    const float* __restrict__ hyper,   // (3, 8, 128)
    float* __restrict__ out)           // (totnatom, 128)
{
    const int tid = threadIdx.x;
    const int la  = tid >> 4;          // local atom 0..7
    const int q   = (tid >> 2) & 3;    // bin quarter 0..3
    const int wj  = tid & 3;           // wave pair index: handles wj and wj+4
    const int a   = blockIdx.x * APB + la;

    __shared__ __align__(16) float4 Tbl[32];                 // {c2,c1,c0,0} per (sp,w)
    __shared__ float Ssm[APB * 4 * QSTRIDE];                 // 10.75 KB (quarters)
    __shared__ __align__(16) float2 Pk[APB / 2][NSYM * NWAVE];   // 2.5 KB packed

    if (tid < 32) {
        const float L2E = 1.4426950408889634f;
        float R = __ldg(&rs[tid]);
        float A = __ldg(&inta[tid]) * L2E;
        float P = __ldg(&params[tid]);
        Tbl[tid] = make_float4(A, -2.f * A * R, A * R * R + __log2f(P), 0.f);
    }
    __syncthreads();

    // ---- Phase 1: per-(atom, quarter, wj) dual-wave moment accumulation ----
    const int n  = g_cnt[a];
    const int nc = min(n, CAP);
    if ((tid & 15) == 0) g_cnt[a] = 0; // reset for next replay

    float acc0[NSYM], acc1[NSYM];
    if (n > CAP && q == 0) {           // overflow init + re-zero (expected never)
        float* gs = (float*)(g_S + (size_t)a * (NSYM * NWAVE / 4));
#pragma unroll
        for (int c = 0; c < NSYM; c++) {
            acc0[c] = gs[c * NWAVE + wj];
            acc1[c] = gs[c * NWAVE + wj + 4];
            gs[c * NWAVE + wj]     = 0.f;
            gs[c * NWAVE + wj + 4] = 0.f;
        }
    } else {
#pragma unroll
        for (int c = 0; c < NSYM; c++) { acc0[c] = 0.f; acc1[c] = 0.f; }
    }

    const float4* rec = g_rec + (size_t)a * CAP;
#pragma unroll 2
    for (int p = q; p < nc; p += 4) {
        float4 r = __ldg(&rec[p]);                 // 4-lane broadcast per record
        unsigned uxb = __float_as_uint(r.x);
        int spb = (int)(uxb & 3u) * NWAVE;
        float ux = __uint_as_float(uxb & ~3u);
        float4 cf0 = Tbl[spb + wj];
        float4 cf1 = Tbl[spb + wj + 4];
        float rc0 = ex2_approx(fmaf(fmaf(cf0.x, r.w, cf0.y), r.w, cf0.z));
        float rc1 = ex2_approx(fmaf(fmaf(cf1.x, r.w, cf1.y), r.w, cf1.z));

        acc0[0] += rc0;                            acc1[0] += rc1;
        float tx0 = rc0 * ux,  ty0 = rc0 * r.y,  tz0 = rc0 * r.z;
        float tx1 = rc1 * ux,  ty1 = rc1 * r.y,  tz1 = rc1 * r.z;
        acc0[1] += tx0;        acc1[1] += tx1;
        acc0[2] += ty0;        acc1[2] += ty1;
        acc0[3] += tz0;        acc1[3] += tz1;
        acc0[4] += tx0 * ux;   acc1[4] += tx1 * ux;
        acc0[5] += tx0 * r.y;  acc1[5] += tx1 * r.y;
        acc0[6] += tx0 * r.z;  acc1[6] += tx1 * r.z;
        acc0[7] += ty0 * r.y;  acc1[7] += ty1 * r.y;
        acc0[8] += ty0 * r.z;  acc1[8] += ty1 * r.z;
        acc0[9] += tz0 * r.z;  acc1[9] += tz1 * r.z;
    }

    // ---- Phase 2: stash quarters, combine into packed pair layout ----
#pragma unroll
    for (int c = 0; c < NSYM; c++) {
        Ssm[(la * 4 + q) * QSTRIDE + c * NWAVE + wj]     = acc0[c];
        Ssm[(la * 4 + q) * QSTRIDE + c * NWAVE + wj + 4] = acc1[c];
    }
    __syncthreads();

    {
        // channel weights {1,1,1,1,1,2,2,1,2,1} -> sqrt folded into S
        const float SQ2 = 1.41421356237309515f;
        const float scl[NSYM] = {1.f, 1.f, 1.f, 1.f, 1.f, SQ2, SQ2, 1.f, SQ2, 1.f};
#pragma unroll
        for (int idx = tid; idx < APB * HSTRIDE; idx += 128) {
            int at = idx / HSTRIDE;
            int cw = idx - at * HSTRIDE;
            float v = Ssm[(at * 4 + 0) * QSTRIDE + cw] + Ssm[(at * 4 + 1) * QSTRIDE + cw]
                    + Ssm[(at * 4 + 2) * QSTRIDE + cw] + Ssm[(at * 4 + 3) * QSTRIDE + cw];
            ((float*)&Pk[at >> 1][cw])[at & 1] = v * scl[cw >> 3];
        }
    }
    __syncthreads();

    // ---- Phase 3: packed f32x2 hyper contraction; thread = orbit column m ----
    const int m = tid;
    unsigned long long hp[3][NWAVE];       // h replicated into both packed halves
#pragma unroll
    for (int k = 0; k < 3; k++)
#pragma unroll
        for (int v = 0; v < NWAVE; v++) {
            float hv = __ldg(&hyper[(k * NWAVE + v) * NORBIT + m]);
            PACK2(hp[k][v], hv, hv);
        }

    const int k_of[NSYM] = {0, 1, 1, 1, 2, 2, 2, 2, 2, 2};

#pragma unroll 1
    for (int pr = 0; pr < APB / 2; pr++) {
        const ulonglong2* S2 = (const ulonglong2*)Pk[pr];
        unsigned long long dens;
        PACK2(dens, 0.f, 0.f);
#pragma unroll
        for (int c = 0; c < NSYM; c++) {
            const int k = k_of[c];
            ulonglong2 q0 = S2[c * 4 + 0];   // packed pairs for w=0,1
            ulonglong2 q1 = S2[c * 4 + 1];   // w=2,3
            ulonglong2 q2 = S2[c * 4 + 2];   // w=4,5
            ulonglong2 q3 = S2[c * 4 + 3];   // w=6,7
            unsigned long long tp;
            MUL_F32X2(tp, q0.x, hp[k][0]);
            FMA_F32X2(tp, q0.y, hp[k][1], tp);
            FMA_F32X2(tp, q1.x, hp[k][2], tp);
            FMA_F32X2(tp, q1.y, hp[k][3], tp);
            FMA_F32X2(tp, q2.x, hp[k][4], tp);
            FMA_F32X2(tp, q2.y, hp[k][5], tp);
            FMA_F32X2(tp, q3.x, hp[k][6], tp);
            FMA_F32X2(tp, q3.y, hp[k][7], tp);
            FMA_F32X2(dens, tp, tp, dens);
        }
        float d0, d1;
        UNPACK2(d0, d1, dens);
        const int a0 = blockIdx.x * APB + 2 * pr;
        out[a0 * NORBIT + m]       = d0;
        out[(a0 + 1) * NORBIT + m] = d1;
    }
}

// ---------------------------------------------------------------------------
// Launch (2 kernels; counters self-reset inside gather)
// ---------------------------------------------------------------------------
extern "C" void kernel_launch(void* const* d_in, const int* in_sizes, int n_in,
                              void* d_out, int out_size) {
    const float* cart       = (const float*)d_in[0];
    // d_in[1] = numatoms (unused by the reference math)
    const int*   species    = (const int*)  d_in[2];
    const int*   atom_index = (const int*)  d_in[3];
    const float* shifts     = (const float*)d_in[4];
    const float* rs         = (const float*)d_in[5];
    const float* inta       = (const float*)d_in[6];
    const float* params     = (const float*)d_in[7];
    const float* hyper      = (const float*)d_in[8];
    float* out = (float*)d_out;

    pair_kernel<<<NN / PBATCH / 256, 256>>>(cart, species, atom_index, shifts,
                                            rs, inta, params);
    gather_kernel<<<TOTNATOM / APB, 128>>>(rs, inta, params, hyper, out);
}